// round 3
// baseline (speedup 1.0000x reference)
#include <cuda_runtime.h>

#define BATCH 4
#define KTGT  64

// ---------------- device-global scratch (no allocations allowed) ----------
__device__ float4   g_tgt[BATCH][KTGT];     // compacted, masked targets (pad=1e18)
__device__ int      g_cnt[BATCH];           // n_valid per batch
__device__ unsigned g_g2p[BATCH][KTGT];     // min ld^2 per (b,k), as ordered u32 bits
__device__ float    g_dist[BATCH];
__device__ float    g_p2g[BATCH];
__device__ float    g_sep[BATCH];

// ---------------- kernel 1: mask/compact targets + zero accumulators ------
__global__ void k_init(const float* __restrict__ tC,
                       const int*   __restrict__ tF,
                       const int*   __restrict__ classes, int nclass)
{
    int tid = threadIdx.x;
    if (tid < BATCH) { g_dist[tid] = 0.f; g_p2g[tid] = 0.f; g_sep[tid] = 0.f; }
    if (tid < BATCH * KTGT) ((unsigned*)g_g2p)[tid] = 0x7f800000u;  // +inf bits

    int w = tid >> 5, lane = tid & 31;
    if (w < BATCH) {
        int cnt = 0;
        #pragma unroll
        for (int half = 0; half < 2; half++) {
            int k = lane + 32 * half;
            int c = tF[w * KTGT + k];
            bool m = false;
            for (int j = 0; j < nclass; j++) m |= (c == __ldg(&classes[j]));
            unsigned bal = __ballot_sync(0xffffffffu, m);
            int pos = cnt + __popc(bal & ((1u << lane) - 1u));
            if (m) {
                const float* p = tC + (w * KTGT + k) * 3;
                g_tgt[w][pos] = make_float4(p[0], p[1], p[2], 0.f);
            }
            cnt += __popc(bal);
        }
        if (lane == 0) g_cnt[w] = cnt;
        for (int k = cnt + lane; k < KTGT; k += 32)
            g_tgt[w][k] = make_float4(1e18f, 1e18f, 1e18f, 0.f);
    }
}

// ---------------- kernel 2: main O(N*K) pass ------------------------------
__global__ void __launch_bounds__(256) k_main(const float* __restrict__ lC,
                                              const float* __restrict__ lF,
                                              int N)
{
    const int b    = blockIdx.y;
    const int tid  = threadIdx.x;
    const int lane = tid & 31;
    const int n    = blockIdx.x * 256 + tid;

    __shared__ float4   s_t[KTGT];
    __shared__ unsigned s_g2p[KTGT];
    __shared__ float    s_red[24];

    if (tid < KTGT) { s_t[tid] = g_tgt[b][tid]; s_g2p[tid] = 0x7f800000u; }
    __syncthreads();

    const int  cnt4  = (g_cnt[b] + 3) & ~3;
    const bool valid = (n < N);

    float cx, cy, cz, d0, fx2, fy2, fz2, f2;
    if (valid) {
        const float* pc = lC + ((size_t)b * N + n) * 3;
        cx = pc[0]; cy = pc[1]; cz = pc[2];
        float4 f = reinterpret_cast<const float4*>(lF)[(size_t)b * N + n];
        d0  = f.x;
        fx2 = 2.f * f.y; fy2 = 2.f * f.z; fz2 = 2.f * f.w;
        f2  = f.y * f.y + f.z * f.z + f.w * f.w;
    } else {
        // far away: contributes only huge values to all mins; dist term masked below
        cx = 1e18f; cy = 0.f; cz = 0.f; d0 = 0.f;
        fx2 = fy2 = fz2 = 0.f; f2 = 0.f;
    }

    float best = 3e38f, second = 3e38f;   // two smallest masked pd^2
    float l2b  = 3e38f, l2s    = 3e38f;   // ld^2 carried at those argmins
    float l2min = 3e38f;                  // min ld^2 (p2g, squared)

    #pragma unroll 4
    for (int k = 0; k < cnt4; k++) {
        float4 t  = s_t[k];                       // LDS.128 broadcast
        float dx  = cx - t.x, dy = cy - t.y, dz = cz - t.z;
        float pd2 = fmaf(dx, dx, fmaf(dy, dy, dz * dz));
        float s   = fmaf(dx, fx2, fmaf(dy, fy2, fmaf(dz, fz2, f2)));
        float ld2 = fmaxf(pd2 + s, 0.f);          // ||C+F'-t||^2, clamped >=0

        l2min = fminf(l2min, ld2);

        bool pb = pd2 < best;
        bool ps = pd2 < second;
        second  = pb ? best : (ps ? pd2 : second);
        l2s     = pb ? l2b  : (ps ? ld2 : l2s);
        best    = pb ? pd2  : best;
        l2b     = pb ? ld2  : l2b;

        // per-target min over landmarks (g2p), u32-ordered for non-negative floats
        unsigned red = __reduce_min_sync(0xffffffffu, __float_as_uint(ld2));
        if (lane == (k & 31)) atomicMin(&s_g2p[k], red);
    }

    float mind = sqrtf(best);
    bool  pm   = mind < 0.1f;
    float tgt  = fminf(mind, 0.2f);
    float diff = d0 - tgt;
    float ad   = fabsf(diff);
    float dl   = (ad < 1.f) ? 0.5f * diff * diff : (ad - 0.5f);
    dl         = valid ? dl : 0.f;
    float p2g2 = pm ? l2min : 0.f;                          // pm => valid
    float sep  = pm ? sqrtf(__fdividef(l2b, l2s)) : 0.f;    // ld(nn1)/ld(nn2)

    // block reduction of the three sums
    #pragma unroll
    for (int o = 16; o > 0; o >>= 1) {
        dl   += __shfl_down_sync(0xffffffffu, dl,   o);
        p2g2 += __shfl_down_sync(0xffffffffu, p2g2, o);
        sep  += __shfl_down_sync(0xffffffffu, sep,  o);
    }
    int wid = tid >> 5;
    if (lane == 0) { s_red[wid] = dl; s_red[8 + wid] = p2g2; s_red[16 + wid] = sep; }
    __syncthreads();

    if (tid < KTGT) atomicMin(&g_g2p[b][tid], s_g2p[tid]);
    if (tid == 0) {
        float a0 = 0.f, a1 = 0.f, a2 = 0.f;
        #pragma unroll
        for (int i = 0; i < 8; i++) { a0 += s_red[i]; a1 += s_red[8 + i]; a2 += s_red[16 + i]; }
        atomicAdd(&g_dist[b], a0);
        atomicAdd(&g_p2g[b],  a1);
        atomicAdd(&g_sep[b],  a2);
    }
}

// ---------------- kernel 3: combine ---------------------------------------
__global__ void k_final(float* __restrict__ out)
{
    __shared__ float s[BATCH * KTGT];
    int tid = threadIdx.x;                 // 256 threads
    int b = tid >> 6, k = tid & 63;
    float v = (k < g_cnt[b]) ? __uint_as_float(g_g2p[b][k]) : 0.f;
    s[tid] = v;
    __syncthreads();
    #pragma unroll
    for (int o = 32; o > 0; o >>= 1) {
        if (k < o) s[tid] += s[tid + o];
        __syncthreads();
    }
    if (tid == 0) {
        float acc = 0.f;
        for (int bb = 0; bb < BATCH; bb++) {
            float g2p2 = s[bb * 64];
            float loss = 0.05f * g_dist[bb]
                       + 0.05f * (g_p2g[bb] + g2p2)
                       + 0.0005f * ((g_cnt[bb] >= 2) ? g_sep[bb] : 0.f);
            acc += loss;
        }
        out[0] = acc * (1.f / BATCH);
    }
}

// ---------------- launch ---------------------------------------------------
extern "C" void kernel_launch(void* const* d_in, const int* in_sizes, int n_in,
                              void* d_out, int out_size)
{
    const float* lC      = (const float*)d_in[0];
    const float* lF      = (const float*)d_in[1];
    const float* tC      = (const float*)d_in[2];
    const int*   tF      = (const int*)d_in[3];
    const int*   classes = (const int*)d_in[4];
    int nclass = in_sizes[4];
    int N      = in_sizes[0] / (BATCH * 3);

    k_init<<<1, 256>>>(tC, tF, classes, nclass);
    dim3 grid((N + 255) / 256, BATCH);
    k_main<<<grid, 256>>>(lC, lF, N);
    k_final<<<1, 256>>>((float*)d_out);
}